// round 3
// baseline (speedup 1.0000x reference)
#include <cuda_runtime.h>
#include <math.h>

// ---------------- problem constants ----------------
#define NS 32768   // samples
#define DD 1024    // feat dim
#define HH 4096    // hidden dim

// ---------------- scratch (alloc-free rule: __device__ globals) ----------------
__device__ float g_S[DD * DD];            // 4 MB   feature scores
__device__ float g_P[DD * DD];            // 4 MB   softmax scores
__device__ float g_attn[(size_t)NS * DD]; // 128 MB attention output
__device__ float g_hid[(size_t)NS * HH];  // 512 MB MLP hidden (also split-K scratch)

// ---------------- tiled fp32 GEMM ----------------
// C[M,N] = epi( sum_k A(m,k) * B(k,n) )
//  TA=false: A stored [M,K] row-major ; TA=true: A stored [K,M] row-major
//  TB=false: B stored [K,N] row-major ; TB=true: B stored [N,K] row-major
//  EPI: 0 = plain store, 1 = split-K slab store (offset by z*M*N),
//       2 = bias + relu, 3 = bias
#define BM 128
#define BN 128
#define BK 16
#define TM 8
#define TN 8
#define PAD 4

template<bool TA, bool TB, int EPI>
__global__ __launch_bounds__(256)
void gemm_kernel(const float* __restrict__ A, const float* __restrict__ B,
                 const float* __restrict__ bias, float* __restrict__ C,
                 int M, int N, int K, int kPer)
{
    __shared__ float As[BK][BM + PAD];
    __shared__ float Bs[BK][BN + PAD];

    const int tid = threadIdx.x;
    const int bm0 = blockIdx.y * BM;
    const int bn0 = blockIdx.x * BN;
    const int kBeg = blockIdx.z * kPer;
    const int kEnd = kBeg + kPer;

    float acc[TM][TN];
    #pragma unroll
    for (int i = 0; i < TM; i++)
        #pragma unroll
        for (int j = 0; j < TN; j++) acc[i][j] = 0.f;

    const int tx = tid & 15;   // 0..15 -> N direction
    const int ty = tid >> 4;   // 0..15 -> M direction

    for (int k0 = kBeg; k0 < kEnd; k0 += BK) {
        // ---- load A tile into As[kk][mm] ----
        if (TA) {
            // A[k, m]: rows are contiguous in m -> vectorized direct store
            #pragma unroll
            for (int r = 0; r < 2; r++) {
                int lin = tid + 256 * r;          // 512 float4s
                int kk  = lin >> 5;               // /32
                int m4  = lin & 31;
                float4 v = *(const float4*)&A[(size_t)(k0 + kk) * M + bm0 + m4 * 4];
                *(float4*)&As[kk][m4 * 4] = v;
            }
        } else {
            // A[m, k]: load 16 contiguous k per row, transpose into smem
            #pragma unroll
            for (int r = 0; r < 2; r++) {
                int lin = tid + 256 * r;
                int mm  = lin >> 2;               // /4
                int k4  = lin & 3;
                float4 v = *(const float4*)&A[(size_t)(bm0 + mm) * K + k0 + k4 * 4];
                As[k4 * 4 + 0][mm] = v.x;
                As[k4 * 4 + 1][mm] = v.y;
                As[k4 * 4 + 2][mm] = v.z;
                As[k4 * 4 + 3][mm] = v.w;
            }
        }
        // ---- load B tile into Bs[kk][nn] ----
        if (TB) {
            // B[n, k]
            #pragma unroll
            for (int r = 0; r < 2; r++) {
                int lin = tid + 256 * r;
                int nn  = lin >> 2;
                int k4  = lin & 3;
                float4 v = *(const float4*)&B[(size_t)(bn0 + nn) * K + k0 + k4 * 4];
                Bs[k4 * 4 + 0][nn] = v.x;
                Bs[k4 * 4 + 1][nn] = v.y;
                Bs[k4 * 4 + 2][nn] = v.z;
                Bs[k4 * 4 + 3][nn] = v.w;
            }
        } else {
            // B[k, n]
            #pragma unroll
            for (int r = 0; r < 2; r++) {
                int lin = tid + 256 * r;
                int kk  = lin >> 5;
                int n4  = lin & 31;
                float4 v = *(const float4*)&B[(size_t)(k0 + kk) * N + bn0 + n4 * 4];
                *(float4*)&Bs[kk][n4 * 4] = v;
            }
        }
        __syncthreads();

        #pragma unroll
        for (int kk = 0; kk < BK; kk++) {
            float a[TM], b[TN];
            #pragma unroll
            for (int i = 0; i < TM; i++) a[i] = As[kk][ty * TM + i];
            #pragma unroll
            for (int j = 0; j < TN; j++) b[j] = Bs[kk][tx * TN + j];
            #pragma unroll
            for (int i = 0; i < TM; i++)
                #pragma unroll
                for (int j = 0; j < TN; j++)
                    acc[i][j] += a[i] * b[j];
        }
        __syncthreads();
    }

    // ---- epilogue ----
    const size_t slab = (EPI == 1) ? (size_t)blockIdx.z * (size_t)M * (size_t)N : 0;
    #pragma unroll
    for (int i = 0; i < TM; i++) {
        int m = bm0 + ty * TM + i;
        #pragma unroll
        for (int j = 0; j < TN; j++) {
            int n = bn0 + tx * TN + j;
            size_t off = (size_t)m * N + n;
            float v = acc[i][j];
            if (EPI == 0)      C[off] = v;
            else if (EPI == 1) C[slab + off] = v;
            else if (EPI == 2) C[off] = fmaxf(v + bias[n], 0.f);
            else               C[off] = v + bias[n];
        }
    }
}

// ---------------- deterministic split-K reduction (8 slabs) ----------------
__global__ void reduce8_kernel(const float* __restrict__ part, float* __restrict__ S)
{
    int i = blockIdx.x * blockDim.x + threadIdx.x;   // 0 .. DD*DD-1
    float s = 0.f;
    #pragma unroll
    for (int z = 0; z < 8; z++) s += part[(size_t)z * (DD * DD) + i];
    S[i] = s;
}

// ---------------- double-exp row softmax ----------------
// logit = exp(s - s*I/sqrt(D));  scores = softmax(logit, axis=-1)
__global__ void softmax_kernel(const float* __restrict__ S, float* __restrict__ P)
{
    const int row = blockIdx.x;       // 0..1023
    const int tid = threadIdx.x;      // 256 threads, 4 cols each
    __shared__ float red[256];

    float l[4];
    float mx = -1e30f;
    #pragma unroll
    for (int r = 0; r < 4; r++) {
        int col = tid + r * 256;
        float s = S[(size_t)row * DD + col];
        float scale = (col == row) ? (1.0f - 1.0f / 32.0f) : 1.0f;  // sqrt(1024)=32
        l[r] = expf(s * scale);       // this is "logit"
        mx = fmaxf(mx, l[r]);
    }
    red[tid] = mx;
    __syncthreads();
    for (int s = 128; s > 0; s >>= 1) {
        if (tid < s) red[tid] = fmaxf(red[tid], red[tid + s]);
        __syncthreads();
    }
    mx = red[0];
    __syncthreads();

    float e[4], sum = 0.f;
    #pragma unroll
    for (int r = 0; r < 4; r++) { e[r] = expf(l[r] - mx); sum += e[r]; }
    red[tid] = sum;
    __syncthreads();
    for (int s = 128; s > 0; s >>= 1) {
        if (tid < s) red[tid] += red[tid + s];
        __syncthreads();
    }
    float inv = 1.0f / red[0];
    #pragma unroll
    for (int r = 0; r < 4; r++) {
        int col = tid + r * 256;
        P[(size_t)row * DD + col] = e[r] * inv;
    }
}

// ---------------- launch ----------------
extern "C" void kernel_launch(void* const* d_in, const int* in_sizes, int n_in,
                              void* d_out, int out_size)
{
    const float* q   = (const float*)d_in[0];
    const float* k   = (const float*)d_in[1];
    const float* v   = (const float*)d_in[2];
    const float* wq1 = (const float*)d_in[3];
    const float* bq1 = (const float*)d_in[4];
    const float* wq2 = (const float*)d_in[5];
    const float* bq2 = (const float*)d_in[6];
    const float* wk1 = (const float*)d_in[7];
    const float* bk1 = (const float*)d_in[8];
    const float* wk2 = (const float*)d_in[9];
    const float* bk2 = (const float*)d_in[10];
    float* out = (float*)d_out;

    float *S, *P, *attn, *hid;
    cudaGetSymbolAddress((void**)&S,    g_S);
    cudaGetSymbolAddress((void**)&P,    g_P);
    cudaGetSymbolAddress((void**)&attn, g_attn);
    cudaGetSymbolAddress((void**)&hid,  g_hid);

    // 1) S = Q^T K  [1024,1024], split-K=8 deterministic slabs into g_hid scratch
    gemm_kernel<true, false, 1><<<dim3(DD / BN, DD / BM, 8), 256>>>(
        q, k, nullptr, hid, DD, DD, NS, NS / 8);
    reduce8_kernel<<<(DD * DD) / 256, 256>>>(hid, S);

    // 2) double-exp softmax -> P
    softmax_kernel<<<DD, 256>>>(S, P);

    // 3) attn = V @ P^T  [32768,1024]
    gemm_kernel<false, true, 0><<<dim3(DD / BN, NS / BM, 1), 256>>>(
        v, P, nullptr, attn, NS, DD, DD, DD);

    // 4) query branch MLP
    gemm_kernel<false, false, 2><<<dim3(HH / BN, NS / BM, 1), 256>>>(
        attn, wq1, bq1, hid, NS, HH, DD, DD);
    gemm_kernel<false, false, 3><<<dim3(DD / BN, NS / BM, 1), 256>>>(
        hid, wq2, bq2, out, NS, DD, HH, HH);

    // 5) key branch MLP
    gemm_kernel<false, false, 2><<<dim3(HH / BN, NS / BM, 1), 256>>>(
        attn, wk1, bk1, hid, NS, HH, DD, DD);
    gemm_kernel<false, false, 3><<<dim3(DD / BN, NS / BM, 1), 256>>>(
        hid, wk2, bk2, out + (size_t)NS * DD, NS, DD, HH, HH);
}